// round 2
// baseline (speedup 1.0000x reference)
#include <cuda_runtime.h>
#include <math.h>

static constexpr int N_ROWS = 16384;
static constexpr int C_COLS = 1000;
static constexpr int C_VEC  = C_COLS / 4;   // 250 float4 per row
static constexpr int WARPS_PER_BLOCK = 8;

__device__ int    g_counts[C_COLS];
__device__ double g_acc;

__global__ void zero_kernel() {
    int i = blockIdx.x * blockDim.x + threadIdx.x;
    if (i < C_COLS) g_counts[i] = 0;
    if (i == 0) g_acc = 0.0;
}

__global__ void hist_kernel(const int* __restrict__ label) {
    int i = blockIdx.x * blockDim.x + threadIdx.x;
    if (i < N_ROWS) {
        int l = label[i];
        if (l >= 0 && l < C_COLS) atomicAdd(&g_counts[l], 1);
    }
}

__global__ __launch_bounds__(WARPS_PER_BLOCK * 32)
void row_kernel(const float* __restrict__ feature,
                const int* __restrict__ label) {
    const int warp_id = threadIdx.x >> 5;
    const int lane    = threadIdx.x & 31;
    const int row     = blockIdx.x * WARPS_PER_BLOCK + warp_id;

    __shared__ float warp_part[WARPS_PER_BLOCK];

    const float4* rp =
        reinterpret_cast<const float4*>(feature + (size_t)row * C_COLS);

    // Load this warp's slice of the row into registers (<= 8 float4 / lane).
    float4 v[8];
    #pragma unroll
    for (int k = 0; k < 8; k++) {
        int idx = lane + k * 32;
        if (idx < C_VEC) v[k] = rp[idx];
        else             v[k] = make_float4(-INFINITY, -INFINITY, -INFINITY, -INFINITY);
    }

    // Row max
    float m = -INFINITY;
    #pragma unroll
    for (int k = 0; k < 8; k++) {
        m = fmaxf(m, fmaxf(fmaxf(v[k].x, v[k].y), fmaxf(v[k].z, v[k].w)));
    }
    #pragma unroll
    for (int o = 16; o > 0; o >>= 1)
        m = fmaxf(m, __shfl_xor_sync(0xFFFFFFFFu, m, o));

    // Row sum of exp(x - m)
    float s = 0.0f;
    #pragma unroll
    for (int k = 0; k < 8; k++) {
        int idx = lane + k * 32;
        if (idx < C_VEC) {
            s += __expf(v[k].x - m) + __expf(v[k].y - m)
               + __expf(v[k].z - m) + __expf(v[k].w - m);
        }
    }
    #pragma unroll
    for (int o = 16; o > 0; o >>= 1)
        s += __shfl_xor_sync(0xFFFFFFFFu, s, o);

    if (lane == 0) {
        int l = label[row];
        if (l < 0) l = 0;
        if (l >= C_COLS) l = C_COLS - 1;
        float xl   = feature[(size_t)row * C_COLS + l];
        float logp = xl - m - __logf(s);
        float p    = __expf(logp);
        float omp  = 1.0f - p;
        float beta = omp * omp;
        float ni   = (float)g_counts[l];
        float r    = ni * (1.0f / (float)N_ROWS);
        float alpha = __expf(r - 1.0f) / r;
        warp_part[warp_id] = alpha * beta * logp;
    }
    __syncthreads();

    if (threadIdx.x == 0) {
        float blk = 0.0f;
        #pragma unroll
        for (int w = 0; w < WARPS_PER_BLOCK; w++) blk += warp_part[w];
        atomicAdd(&g_acc, (double)blk);
    }
}

__global__ void finalize_kernel(float* __restrict__ out) {
    out[0] = (float)(-g_acc / (double)N_ROWS);
}

extern "C" void kernel_launch(void* const* d_in, const int* in_sizes, int n_in,
                              void* d_out, int out_size) {
    const float* feature = (const float*)d_in[0];
    const int*   label   = (const int*)d_in[1];
    float*       out     = (float*)d_out;

    zero_kernel<<<(C_COLS + 255) / 256, 256>>>();
    hist_kernel<<<(N_ROWS + 255) / 256, 256>>>(label);
    row_kernel<<<N_ROWS / WARPS_PER_BLOCK, WARPS_PER_BLOCK * 32>>>(feature, label);
    finalize_kernel<<<1, 1>>>(out);
}